// round 14
// baseline (speedup 1.0000x reference)
#include <cuda_runtime.h>
#include <cuda_fp16.h>
#include <mma.h>
#include <math.h>
#include <cstdint>

using namespace nvcuda;

// Problem constants (fixed by the dataset)
#define N_NODES 50000
#define DIM     128
#define N_EDGES 640000

// GEMM: block = 256 thr (8 warps), tile 64 rows x 128 cols, raw mma.m16n8k8.tf32
#define TM 64
#define SW_FLOATS 16384                   // W fragment-ordered: [16 nf][16 kk][32 lane][2]
#define SA_STRIDE 132                     // kk-stride in floats (128 + 4 pad)
#define SA_FLOATS (64 * SA_STRIDE)
#define GEMM_SMEM ((SW_FLOATS + SA_FLOATS) * 4)   // 99328 B -> 2 blocks/SM

// ---------------- scratch (device globals; no allocation allowed) ----------------
__device__ uint2 g_hWh[N_NODES*32];       // hW in fp16 (gather table; 256B/row)
__device__ float g_y1 [N_NODES*DIM];      // y1 fp32 (self-term + final concat)
__device__ uint2 g_y1h[N_NODES*32];       // y1 in fp16 (gather table)
__device__ uint2 g_zh [N_NODES*32];       // z in fp16 (only consumed by tf32 GEMM)
__device__ float g_ev [N_EDGES];
__device__ float g_Wp1[SW_FLOATS];        // W1 (BN1-folded, tf32) in B-fragment order
__device__ float g_Wpd[SW_FLOATS];        // Wd (tf32) in B-fragment order
__device__ float g_b1p[DIM];              // bias from BN1 shift: sum_k t1[k]*W1[k][n]
__device__ int   g_rowptr[N_NODES+1];
__device__ float g_s2[DIM], g_t2[DIM];

__device__ __forceinline__ void cp_async16(uint32_t smem_addr, const void* gptr) {
    asm volatile("cp.async.cg.shared.global [%0], [%1], 16;\n"
                 :: "r"(smem_addr), "l"(gptr) : "memory");
}
__device__ __forceinline__ void cp_async_commit() {
    asm volatile("cp.async.commit_group;\n" ::: "memory");
}
__device__ __forceinline__ void cp_async_wait_all() {
    asm volatile("cp.async.wait_group 0;\n" ::: "memory");
}

__device__ __forceinline__ void mma_tf32(float acc[4], const uint32_t a[4], const uint32_t b[2]) {
    asm volatile("mma.sync.aligned.m16n8k8.row.col.f32.tf32.tf32.f32 "
                 "{%0,%1,%2,%3}, {%4,%5,%6,%7}, {%8,%9}, {%0,%1,%2,%3};"
                 : "+f"(acc[0]), "+f"(acc[1]), "+f"(acc[2]), "+f"(acc[3])
                 : "r"(a[0]), "r"(a[1]), "r"(a[2]), "r"(a[3]), "r"(b[0]), "r"(b[1]));
}

__device__ __forceinline__ float4 h2f4(uint2 h) {
    float2 a = __half22float2(*reinterpret_cast<__half2*>(&h.x));
    float2 b = __half22float2(*reinterpret_cast<__half2*>(&h.y));
    return make_float4(a.x, a.y, b.x, b.y);
}

// ---------------- 1: fused prep: BN fold + W permute + bias fold + rowptr -------
__global__ void prep_all(const float* __restrict__ g1, const float* __restrict__ b1,
                         const float* __restrict__ m1, const float* __restrict__ v1,
                         const float* __restrict__ g2, const float* __restrict__ b2,
                         const float* __restrict__ m2, const float* __restrict__ v2,
                         const float* __restrict__ W1, const float* __restrict__ Wd,
                         const int* __restrict__ rows, int n, int e)
{
    int i = blockIdx.x * blockDim.x + threadIdx.x;

    if (i < DIM) {
        float s2 = g2[i] * rsqrtf(v2[i] + 1e-3f);
        g_s2[i] = s2; g_t2[i] = b2[i] - m2[i] * s2;
        float s = 0.f;
        for (int k = 0; k < DIM; k++) {
            float s1k = g1[k] * rsqrtf(v1[k] + 1e-3f);
            float t1k = b1[k] - m1[k] * s1k;
            s += t1k * W1[k * DIM + i];
        }
        g_b1p[i] = s;
    }
    if (i < SW_FLOATS) {
        int t    = i & 1;
        int lane = (i >> 1) & 31;
        int kk   = (i >> 6) & 15;
        int nf   = i >> 10;
        int k  = kk * 8 + (lane & 3) + 4 * t;
        int nn = nf * 8 + (lane >> 2);
        float s1k = g1[k] * rsqrtf(v1[k] + 1e-3f);
        g_Wp1[i] = wmma::__float_to_tf32(s1k * W1[k * DIM + nn]);
        g_Wpd[i] = wmma::__float_to_tf32(Wd[k * DIM + nn]);
    }
    if (i <= n) {
        int lo = 0, hi = e;
        while (lo < hi) {
            int mid = (lo + hi) >> 1;
            if (rows[mid] < i) lo = mid + 1; else hi = mid;
        }
        g_rowptr[i] = lo;
    }
}

// ----- GEMM core (fp32 A): fragment-ordered smem, raw mma; fills acc[8][4] ------
__device__ __forceinline__ void gemm_mma_core_f32(
    float* sW, float* sA,
    const float* __restrict__ A, const float* __restrict__ Wp,
    int r0, int n, int tid, float acc[8][4])
{
    uint32_t swb = (uint32_t)__cvta_generic_to_shared(sW);
    const float4* W4 = (const float4*)Wp;
    #pragma unroll
    for (int k = 0; k < 16; k++) {
        int idx = tid + k * 256;
        cp_async16(swb + idx * 16, W4 + idx);
    }
    cp_async_commit();

    #pragma unroll
    for (int k = 0; k < 8; k++) {
        int idx = tid + k * 256;
        int row = idx >> 5, q = idx & 31;
        int gr = r0 + row;
        float4 a = make_float4(0.f, 0.f, 0.f, 0.f);
        if (gr < n) a = ((const float4*)A)[gr * 32 + q];
        a.x = wmma::__float_to_tf32(a.x);
        a.y = wmma::__float_to_tf32(a.y);
        a.z = wmma::__float_to_tf32(a.z);
        a.w = wmma::__float_to_tf32(a.w);
        int mg = row >> 4, g = row & 7, jr = (row >> 3) & 1;
        int kk = q >> 1, j = (q & 1) * 2 + jr;
        float* dst = &sA[(mg * 16 + kk) * SA_STRIDE + j];
        dst[(g * 4 + 0) * 4] = a.x;
        dst[(g * 4 + 1) * 4] = a.y;
        dst[(g * 4 + 2) * 4] = a.z;
        dst[(g * 4 + 3) * 4] = a.w;
    }
    cp_async_wait_all();
    __syncthreads();

    const int wid = tid >> 5, lane = tid & 31;
    const int mg = wid >> 1, nh = wid & 1;
    #pragma unroll
    for (int nf = 0; nf < 8; nf++)
        acc[nf][0] = acc[nf][1] = acc[nf][2] = acc[nf][3] = 0.f;

    #pragma unroll
    for (int kk = 0; kk < 16; kk++) {
        uint32_t au[4];
        float4 av = *(const float4*)&sA[(mg * 16 + kk) * SA_STRIDE + lane * 4];
        au[0] = __float_as_uint(av.x); au[1] = __float_as_uint(av.y);
        au[2] = __float_as_uint(av.z); au[3] = __float_as_uint(av.w);
        #pragma unroll
        for (int nf = 0; nf < 8; nf++) {
            uint32_t bu[2];
            float2 bv = *(const float2*)&sW[((nh * 8 + nf) * 16 + kk) * 64 + lane * 2];
            bu[0] = __float_as_uint(bv.x); bu[1] = __float_as_uint(bv.y);
            mma_tf32(acc[nf], au, bu);
        }
    }
    __syncthreads();
}

// ----- GEMM core (fp16 A source): same, but A is uint2/half2 rows ---------------
__device__ __forceinline__ void gemm_mma_core_f16(
    float* sW, float* sA,
    const uint2* __restrict__ Ah, const float* __restrict__ Wp,
    int r0, int n, int tid, float acc[8][4])
{
    uint32_t swb = (uint32_t)__cvta_generic_to_shared(sW);
    const float4* W4 = (const float4*)Wp;
    #pragma unroll
    for (int k = 0; k < 16; k++) {
        int idx = tid + k * 256;
        cp_async16(swb + idx * 16, W4 + idx);
    }
    cp_async_commit();

    #pragma unroll
    for (int k = 0; k < 8; k++) {
        int idx = tid + k * 256;
        int row = idx >> 5, q = idx & 31;
        int gr = r0 + row;
        float4 a = make_float4(0.f, 0.f, 0.f, 0.f);
        if (gr < n) a = h2f4(Ah[gr * 32 + q]);   // fp16 -> fp32 (exact); tf32 round below
        a.x = wmma::__float_to_tf32(a.x);
        a.y = wmma::__float_to_tf32(a.y);
        a.z = wmma::__float_to_tf32(a.z);
        a.w = wmma::__float_to_tf32(a.w);
        int mg = row >> 4, g = row & 7, jr = (row >> 3) & 1;
        int kk = q >> 1, j = (q & 1) * 2 + jr;
        float* dst = &sA[(mg * 16 + kk) * SA_STRIDE + j];
        dst[(g * 4 + 0) * 4] = a.x;
        dst[(g * 4 + 1) * 4] = a.y;
        dst[(g * 4 + 2) * 4] = a.z;
        dst[(g * 4 + 3) * 4] = a.w;
    }
    cp_async_wait_all();
    __syncthreads();

    const int wid = tid >> 5, lane = tid & 31;
    const int mg = wid >> 1, nh = wid & 1;
    #pragma unroll
    for (int nf = 0; nf < 8; nf++)
        acc[nf][0] = acc[nf][1] = acc[nf][2] = acc[nf][3] = 0.f;

    #pragma unroll
    for (int kk = 0; kk < 16; kk++) {
        uint32_t au[4];
        float4 av = *(const float4*)&sA[(mg * 16 + kk) * SA_STRIDE + lane * 4];
        au[0] = __float_as_uint(av.x); au[1] = __float_as_uint(av.y);
        au[2] = __float_as_uint(av.z); au[3] = __float_as_uint(av.w);
        #pragma unroll
        for (int nf = 0; nf < 8; nf++) {
            uint32_t bu[2];
            float2 bv = *(const float2*)&sW[((nh * 8 + nf) * 16 + kk) * 64 + lane * 2];
            bu[0] = __float_as_uint(bv.x); bu[1] = __float_as_uint(bv.y);
            mma_tf32(acc[nf], au, bu);
        }
    }
    __syncthreads();
}

// ---------------- 2: hW(fp16) = x @ W1' + b1p  (BN1 folded into W1') ------------
__global__ void __launch_bounds__(256, 2)
gemm128_a(const float* __restrict__ A, const float* __restrict__ Wp,
          const float* __restrict__ bias, __half2* __restrict__ Ch, int n)
{
    extern __shared__ float sh[];
    float* sW = sh;
    float* sA = sh + SW_FLOATS;
    const int tid = threadIdx.x;
    const int r0  = blockIdx.x * TM;

    float acc[8][4];
    gemm_mma_core_f32(sW, sA, A, Wp, r0, n, tid, acc);

    const int wid = tid >> 5, lane = tid & 31;
    const int mg = wid >> 1, nh = wid & 1;
    const int g = lane >> 2, c = lane & 3;
    int r_lo = r0 + mg * 16 + g;
    #pragma unroll
    for (int nf = 0; nf < 8; nf++) {
        int col = nh * 64 + nf * 8 + c * 2;
        float2 bp = *(const float2*)&bias[col];
        if (r_lo < n)
            Ch[r_lo * 64 + (col >> 1)] =
                __floats2half2_rn(acc[nf][0] + bp.x, acc[nf][1] + bp.y);
        if (r_lo + 8 < n)
            Ch[(r_lo + 8) * 64 + (col >> 1)] =
                __floats2half2_rn(acc[nf][2] + bp.x, acc[nf][3] + bp.y);
    }
}

// ---------------- 3: y1 = tanh(A @ hW + b1), ALSO computes g_ev -----------------
// hW gathered in fp16 (256B/row), accumulate fp32, 8-deep gather pipeline.
__global__ void spmm_tanh(const uint2* __restrict__ Hh, const int* __restrict__ cols,
                          const float* __restrict__ vals, const int* __restrict__ rel,
                          const float* __restrict__ relc, const float* __restrict__ b1,
                          float* __restrict__ y1f, uint2* __restrict__ y1h, int n)
{
    int w = (blockIdx.x * blockDim.x + threadIdx.x) >> 5;
    int lane = threadIdx.x & 31;
    if (w >= n) return;
    int s = g_rowptr[w], e = g_rowptr[w + 1];
    float4 acc = make_float4(0.f, 0.f, 0.f, 0.f);
    for (int base = s; base < e; base += 32) {
        int idx = base + lane;
        int   cl = 0; float vl = 0.f;
        if (idx < e) {
            cl = __ldg(&cols[idx]);
            vl = __ldg(&vals[idx]);
            g_ev[idx] = vl / (__ldg(&relc[__ldg(&rel[idx])]) + 1.f);
        }
        int m = min(32, e - base);
        int j = 0;
        for (; j + 8 <= m; j += 8) {
            int   cs[8]; float vs[8]; float4 hs[8];
            #pragma unroll
            for (int u = 0; u < 8; u++) {
                cs[u] = __shfl_sync(0xffffffffu, cl, j + u);
                vs[u] = __shfl_sync(0xffffffffu, vl, j + u);
            }
            #pragma unroll
            for (int u = 0; u < 8; u++) hs[u] = h2f4(Hh[cs[u] * 32 + lane]);
            #pragma unroll
            for (int u = 0; u < 8; u++) {
                acc.x += vs[u] * hs[u].x; acc.y += vs[u] * hs[u].y;
                acc.z += vs[u] * hs[u].z; acc.w += vs[u] * hs[u].w;
            }
        }
        for (; j < m; j++) {
            int   c = __shfl_sync(0xffffffffu, cl, j);
            float v = __shfl_sync(0xffffffffu, vl, j);
            float4 h = h2f4(Hh[c * 32 + lane]);
            acc.x += v * h.x; acc.y += v * h.y; acc.z += v * h.z; acc.w += v * h.w;
        }
    }
    float4 b = ((const float4*)b1)[lane];
    float4 o = make_float4(tanhf(acc.x + b.x), tanhf(acc.y + b.y),
                           tanhf(acc.z + b.z), tanhf(acc.w + b.w));
    ((float4*)y1f)[w * 32 + lane] = o;
    uint2 oh;
    *reinterpret_cast<__half2*>(&oh.x) = __floats2half2_rn(o.x, o.y);
    *reinterpret_cast<__half2*>(&oh.y) = __floats2half2_rn(o.z, o.w);
    y1h[w * 32 + lane] = oh;
}

// ---------------- 4: z(fp16) = A_rel @ BN2(y1) + BN2(y1)*(ck+1) -----------------
__global__ void spmm_rgin(const float* __restrict__ y1f, const uint2* __restrict__ Yh,
                          const int* __restrict__ cols, const float* __restrict__ ev,
                          const float* __restrict__ ck, uint2* __restrict__ zh, int n)
{
    int w = (blockIdx.x * blockDim.x + threadIdx.x) >> 5;
    int lane = threadIdx.x & 31;
    if (w >= n) return;
    int s = g_rowptr[w], e = g_rowptr[w + 1];
    float4 accA = make_float4(0.f, 0.f, 0.f, 0.f);
    float  accB = 0.f;
    for (int base = s; base < e; base += 32) {
        int idx = base + lane;
        int cl = 0; float el = 0.f;
        if (idx < e) { cl = __ldg(&cols[idx]); el = __ldg(&ev[idx]); }
        int m = min(32, e - base);
        int j = 0;
        for (; j + 8 <= m; j += 8) {
            int   cs[8]; float es[8]; float4 hs[8];
            #pragma unroll
            for (int u = 0; u < 8; u++) {
                cs[u] = __shfl_sync(0xffffffffu, cl, j + u);
                es[u] = __shfl_sync(0xffffffffu, el, j + u);
            }
            #pragma unroll
            for (int u = 0; u < 8; u++) hs[u] = h2f4(Yh[cs[u] * 32 + lane]);
            #pragma unroll
            for (int u = 0; u < 8; u++) {
                accA.x += es[u] * hs[u].x; accA.y += es[u] * hs[u].y;
                accA.z += es[u] * hs[u].z; accA.w += es[u] * hs[u].w;
                accB += es[u];
            }
        }
        for (; j < m; j++) {
            int   c  = __shfl_sync(0xffffffffu, cl, j);
            float ee = __shfl_sync(0xffffffffu, el, j);
            float4 h = h2f4(Yh[c * 32 + lane]);
            accA.x += ee * h.x; accA.y += ee * h.y;
            accA.z += ee * h.z; accA.w += ee * h.w;
            accB += ee;
        }
    }
    int d = lane * 4;
    float4 s2 = *(const float4*)&g_s2[d];
    float4 t2 = *(const float4*)&g_t2[d];
    float4 yr = ((const float4*)y1f)[w * 32 + lane];   // self-term in fp32
    float  cm = __ldg(&ck[w]) + 1.f;
    float4 o;
    o.x = s2.x * accA.x + t2.x * accB + (yr.x * s2.x + t2.x) * cm;
    o.y = s2.y * accA.y + t2.y * accB + (yr.y * s2.y + t2.y) * cm;
    o.z = s2.z * accA.z + t2.z * accB + (yr.z * s2.z + t2.z) * cm;
    o.w = s2.w * accA.w + t2.w * accB + (yr.w * s2.w + t2.w) * cm;
    uint2 oh;
    *reinterpret_cast<__half2*>(&oh.x) = __floats2half2_rn(o.x, o.y);
    *reinterpret_cast<__half2*>(&oh.y) = __floats2half2_rn(o.z, o.w);
    zh[w * 32 + lane] = oh;
}

// -------- 5: gemm2 (z @ Wd' + bd) FUSED with final l2-normalize-concat ----------
__global__ void __launch_bounds__(256, 2)
gemm128_norm(const uint2* __restrict__ Ah, const float* __restrict__ Wp,
             const float* __restrict__ bias,
             const float* __restrict__ x, const float* __restrict__ y1,
             float* __restrict__ out, int n)
{
    extern __shared__ float sh[];
    float* sW = sh;
    float* sA = sh + SW_FLOATS;
    const int tid = threadIdx.x;
    const int r0  = blockIdx.x * TM;

    float acc[8][4];
    gemm_mma_core_f16(sW, sA, Ah, Wp, r0, n, tid, acc);

    const int wid = tid >> 5, lane = tid & 31;
    const int mg = wid >> 1, nh = wid & 1;
    const int g = lane >> 2, c = lane & 3;
    #pragma unroll
    for (int nf = 0; nf < 8; nf++) {
        int col = nh * 64 + nf * 8 + c * 2;
        int lr = mg * 16 + g;
        *(float2*)&sA[lr * SA_STRIDE + col]       = make_float2(acc[nf][0], acc[nf][1]);
        *(float2*)&sA[(lr + 8) * SA_STRIDE + col] = make_float2(acc[nf][2], acc[nf][3]);
    }
    __syncthreads();

    float4 bv = ((const float4*)bias)[lane];
    #pragma unroll
    for (int rr = 0; rr < 8; rr++) {
        int row = wid * 8 + rr;
        int gr  = r0 + row;
        if (gr >= n) continue;
        float4 cc = *(float4*)&sA[row * SA_STRIDE + lane * 4];
        cc.x += bv.x; cc.y += bv.y; cc.z += bv.z; cc.w += bv.w;
        float4 a = ((const float4*)x )[gr * 32 + lane];
        float4 b = ((const float4*)y1)[gr * 32 + lane];
        float sa = a.x*a.x + a.y*a.y + a.z*a.z + a.w*a.w;
        float sb = b.x*b.x + b.y*b.y + b.z*b.z + b.w*b.w;
        float sc = cc.x*cc.x + cc.y*cc.y + cc.z*cc.z + cc.w*cc.w;
        #pragma unroll
        for (int o = 16; o; o >>= 1) {
            sa += __shfl_xor_sync(0xffffffffu, sa, o);
            sb += __shfl_xor_sync(0xffffffffu, sb, o);
            sc += __shfl_xor_sync(0xffffffffu, sc, o);
        }
        float ra = rsqrtf(fmaxf(sa, 1e-12f));
        float rb = rsqrtf(fmaxf(sb, 1e-12f));
        float rc = rsqrtf(fmaxf(sc, 1e-12f));
        float na = sa * ra * ra, nb = sb * rb * rb, nc = sc * rc * rc;
        float rt = rsqrtf(fmaxf(na + nb + nc, 1e-12f));
        float fa = ra * rt, fb = rb * rt, fc = rc * rt;
        float4* O = (float4*)out;
        int obase = gr * 96;
        O[obase + lane]      = make_float4(a.x*fa, a.y*fa, a.z*fa, a.w*fa);
        O[obase + 32 + lane] = make_float4(b.x*fb, b.y*fb, b.z*fb, b.w*fb);
        O[obase + 64 + lane] = make_float4(cc.x*fc, cc.y*fc, cc.z*fc, cc.w*fc);
    }
}

// ---------------- launch --------------------------------------------------------
extern "C" void kernel_launch(void* const* d_in, const int* in_sizes, int n_in,
                              void* d_out, int out_size)
{
    const float* x      = (const float*)d_in[0];
    const int*   rows   = (const int*)  d_in[1];
    const int*   cols   = (const int*)  d_in[2];
    const float* adj    = (const float*)d_in[3];
    const int*   rel    = (const int*)  d_in[4];
    const float* gamma1 = (const float*)d_in[5];
    const float* beta1  = (const float*)d_in[6];
    const float* mean1  = (const float*)d_in[7];
    const float* var1   = (const float*)d_in[8];
    const float* W1     = (const float*)d_in[9];
    const float* b1     = (const float*)d_in[10];
    const float* gamma2 = (const float*)d_in[11];
    const float* beta2  = (const float*)d_in[12];
    const float* mean2  = (const float*)d_in[13];
    const float* var2   = (const float*)d_in[14];
    const float* relc   = (const float*)d_in[15];
    const float* ck     = (const float*)d_in[16];
    const float* Wd     = (const float*)d_in[17];
    const float* bd     = (const float*)d_in[18];
    float* out = (float*)d_out;

    const int n = in_sizes[0] / DIM;     // 50000
    const int e = in_sizes[1];           // 640000

    cudaFuncSetAttribute(gemm128_a,    cudaFuncAttributeMaxDynamicSharedMemorySize, GEMM_SMEM);
    cudaFuncSetAttribute(gemm128_norm, cudaFuncAttributeMaxDynamicSharedMemorySize, GEMM_SMEM);

    // __device__ symbols are NOT valid host-side pointers — fetch device addresses.
    float *y1, *ev, *Wp1, *Wpd, *b1p;
    uint2 *hWh, *y1h, *zh;
    cudaGetSymbolAddress((void**)&hWh, g_hWh);
    cudaGetSymbolAddress((void**)&y1,  g_y1);
    cudaGetSymbolAddress((void**)&y1h, g_y1h);
    cudaGetSymbolAddress((void**)&zh,  g_zh);
    cudaGetSymbolAddress((void**)&ev,  g_ev);
    cudaGetSymbolAddress((void**)&Wp1, g_Wp1);
    cudaGetSymbolAddress((void**)&Wpd, g_Wpd);
    cudaGetSymbolAddress((void**)&b1p, g_b1p);

    int prep_threads = (n + 1 > SW_FLOATS) ? n + 1 : SW_FLOATS;
    prep_all<<<(prep_threads + 255) / 256, 256>>>(gamma1, beta1, mean1, var1,
                                                  gamma2, beta2, mean2, var2,
                                                  W1, Wd, rows, n, e);

    int gemm_blocks = (n + TM - 1) / TM;
    gemm128_a<<<gemm_blocks, 256, GEMM_SMEM>>>(x, Wp1, b1p, (__half2*)hWh, n);

    int warp_blocks = (n * 32 + 255) / 256;
    spmm_tanh<<<warp_blocks, 256>>>(hWh, cols, adj, rel, relc, b1, y1, y1h, n);
    spmm_rgin<<<warp_blocks, 256>>>(y1, y1h, cols, ev, ck, zh, n);

    gemm128_norm<<<gemm_blocks, 256, GEMM_SMEM>>>(zh, Wpd, bd, x, y1, out, n);
}

// round 15
// speedup vs baseline: 1.0601x; 1.0601x over previous
#include <cuda_runtime.h>
#include <cuda_fp16.h>
#include <mma.h>
#include <math.h>
#include <cstdint>

using namespace nvcuda;

// Problem constants (fixed by the dataset)
#define N_NODES 50000
#define DIM     128
#define N_EDGES 640000

// GEMM: block = 256 thr (8 warps), tile 64 rows x 128 cols, raw mma.m16n8k8.tf32
#define TM 64
#define SW_FLOATS 16384                   // W fragment-ordered: [16 nf][16 kk][32 lane][2]
#define SA_STRIDE 132                     // kk-stride in floats (128 + 4 pad)
#define SA_FLOATS (64 * SA_STRIDE)
#define GEMM_SMEM ((SW_FLOATS + SA_FLOATS) * 4)   // 99328 B -> 2 blocks/SM

// ---------------- scratch (device globals; no allocation allowed) ----------------
__device__ uint2 g_hWh[N_NODES*32];       // hW in fp16 (gather table; 256B/row)
__device__ float g_y1 [N_NODES*DIM];      // y1 fp32 (self-term + final concat)
__device__ uint2 g_y1h[N_NODES*32];       // y1 in fp16 (gather table)
__device__ uint2 g_zh [N_NODES*32];       // z in fp16 (only consumed by tf32 GEMM)
__device__ float g_ev [N_EDGES];
__device__ float g_Wp1[SW_FLOATS];        // W1 (BN1-folded, tf32) in B-fragment order
__device__ float g_Wpd[SW_FLOATS];        // Wd (tf32) in B-fragment order
__device__ float g_b1p[DIM];              // bias from BN1 shift: sum_k t1[k]*W1[k][n]
__device__ int   g_rowptr[N_NODES+1];
__device__ float g_s2[DIM], g_t2[DIM];

__device__ __forceinline__ void cp_async16(uint32_t smem_addr, const void* gptr) {
    asm volatile("cp.async.cg.shared.global [%0], [%1], 16;\n"
                 :: "r"(smem_addr), "l"(gptr) : "memory");
}
__device__ __forceinline__ void cp_async_commit() {
    asm volatile("cp.async.commit_group;\n" ::: "memory");
}
__device__ __forceinline__ void cp_async_wait_all() {
    asm volatile("cp.async.wait_group 0;\n" ::: "memory");
}

__device__ __forceinline__ void mma_tf32(float acc[4], const uint32_t a[4], const uint32_t b[2]) {
    asm volatile("mma.sync.aligned.m16n8k8.row.col.f32.tf32.tf32.f32 "
                 "{%0,%1,%2,%3}, {%4,%5,%6,%7}, {%8,%9}, {%0,%1,%2,%3};"
                 : "+f"(acc[0]), "+f"(acc[1]), "+f"(acc[2]), "+f"(acc[3])
                 : "r"(a[0]), "r"(a[1]), "r"(a[2]), "r"(a[3]), "r"(b[0]), "r"(b[1]));
}

__device__ __forceinline__ float4 h2f4(uint2 h) {
    float2 a = __half22float2(*reinterpret_cast<__half2*>(&h.x));
    float2 b = __half22float2(*reinterpret_cast<__half2*>(&h.y));
    return make_float4(a.x, a.y, b.x, b.y);
}

// ---------------- 1: fused prep: BN fold + W permute + bias fold + rowptr -------
__global__ void prep_all(const float* __restrict__ g1, const float* __restrict__ b1,
                         const float* __restrict__ m1, const float* __restrict__ v1,
                         const float* __restrict__ g2, const float* __restrict__ b2,
                         const float* __restrict__ m2, const float* __restrict__ v2,
                         const float* __restrict__ W1, const float* __restrict__ Wd,
                         const int* __restrict__ rows, int n, int e)
{
    int i = blockIdx.x * blockDim.x + threadIdx.x;

    if (i < DIM) {
        float s2 = g2[i] * rsqrtf(v2[i] + 1e-3f);
        g_s2[i] = s2; g_t2[i] = b2[i] - m2[i] * s2;
        float s = 0.f;
        for (int k = 0; k < DIM; k++) {
            float s1k = g1[k] * rsqrtf(v1[k] + 1e-3f);
            float t1k = b1[k] - m1[k] * s1k;
            s += t1k * W1[k * DIM + i];
        }
        g_b1p[i] = s;
    }
    if (i < SW_FLOATS) {
        int t    = i & 1;
        int lane = (i >> 1) & 31;
        int kk   = (i >> 6) & 15;
        int nf   = i >> 10;
        int k  = kk * 8 + (lane & 3) + 4 * t;
        int nn = nf * 8 + (lane >> 2);
        float s1k = g1[k] * rsqrtf(v1[k] + 1e-3f);
        g_Wp1[i] = wmma::__float_to_tf32(s1k * W1[k * DIM + nn]);
        g_Wpd[i] = wmma::__float_to_tf32(Wd[k * DIM + nn]);
    }
    if (i <= n) {
        int lo = 0, hi = e;
        while (lo < hi) {
            int mid = (lo + hi) >> 1;
            if (rows[mid] < i) lo = mid + 1; else hi = mid;
        }
        g_rowptr[i] = lo;
    }
}

// ----- GEMM core (fp32 A): fragment-ordered smem, raw mma; fills acc[8][4] ------
__device__ __forceinline__ void gemm_mma_core_f32(
    float* sW, float* sA,
    const float* __restrict__ A, const float* __restrict__ Wp,
    int r0, int n, int tid, float acc[8][4])
{
    uint32_t swb = (uint32_t)__cvta_generic_to_shared(sW);
    const float4* W4 = (const float4*)Wp;
    #pragma unroll
    for (int k = 0; k < 16; k++) {
        int idx = tid + k * 256;
        cp_async16(swb + idx * 16, W4 + idx);
    }
    cp_async_commit();

    #pragma unroll
    for (int k = 0; k < 8; k++) {
        int idx = tid + k * 256;
        int row = idx >> 5, q = idx & 31;
        int gr = r0 + row;
        float4 a = make_float4(0.f, 0.f, 0.f, 0.f);
        if (gr < n) a = ((const float4*)A)[gr * 32 + q];
        a.x = wmma::__float_to_tf32(a.x);
        a.y = wmma::__float_to_tf32(a.y);
        a.z = wmma::__float_to_tf32(a.z);
        a.w = wmma::__float_to_tf32(a.w);
        int mg = row >> 4, g = row & 7, jr = (row >> 3) & 1;
        int kk = q >> 1, j = (q & 1) * 2 + jr;
        float* dst = &sA[(mg * 16 + kk) * SA_STRIDE + j];
        dst[(g * 4 + 0) * 4] = a.x;
        dst[(g * 4 + 1) * 4] = a.y;
        dst[(g * 4 + 2) * 4] = a.z;
        dst[(g * 4 + 3) * 4] = a.w;
    }
    cp_async_wait_all();
    __syncthreads();

    const int wid = tid >> 5, lane = tid & 31;
    const int mg = wid >> 1, nh = wid & 1;
    #pragma unroll
    for (int nf = 0; nf < 8; nf++)
        acc[nf][0] = acc[nf][1] = acc[nf][2] = acc[nf][3] = 0.f;

    #pragma unroll
    for (int kk = 0; kk < 16; kk++) {
        uint32_t au[4];
        float4 av = *(const float4*)&sA[(mg * 16 + kk) * SA_STRIDE + lane * 4];
        au[0] = __float_as_uint(av.x); au[1] = __float_as_uint(av.y);
        au[2] = __float_as_uint(av.z); au[3] = __float_as_uint(av.w);
        #pragma unroll
        for (int nf = 0; nf < 8; nf++) {
            uint32_t bu[2];
            float2 bv = *(const float2*)&sW[((nh * 8 + nf) * 16 + kk) * 64 + lane * 2];
            bu[0] = __float_as_uint(bv.x); bu[1] = __float_as_uint(bv.y);
            mma_tf32(acc[nf], au, bu);
        }
    }
    __syncthreads();
}

// ----- GEMM core (fp16 A source): same, but A is uint2/half2 rows ---------------
__device__ __forceinline__ void gemm_mma_core_f16(
    float* sW, float* sA,
    const uint2* __restrict__ Ah, const float* __restrict__ Wp,
    int r0, int n, int tid, float acc[8][4])
{
    uint32_t swb = (uint32_t)__cvta_generic_to_shared(sW);
    const float4* W4 = (const float4*)Wp;
    #pragma unroll
    for (int k = 0; k < 16; k++) {
        int idx = tid + k * 256;
        cp_async16(swb + idx * 16, W4 + idx);
    }
    cp_async_commit();

    #pragma unroll
    for (int k = 0; k < 8; k++) {
        int idx = tid + k * 256;
        int row = idx >> 5, q = idx & 31;
        int gr = r0 + row;
        float4 a = make_float4(0.f, 0.f, 0.f, 0.f);
        if (gr < n) a = h2f4(Ah[gr * 32 + q]);   // fp16 -> fp32 exact; tf32 round below
        a.x = wmma::__float_to_tf32(a.x);
        a.y = wmma::__float_to_tf32(a.y);
        a.z = wmma::__float_to_tf32(a.z);
        a.w = wmma::__float_to_tf32(a.w);
        int mg = row >> 4, g = row & 7, jr = (row >> 3) & 1;
        int kk = q >> 1, j = (q & 1) * 2 + jr;
        float* dst = &sA[(mg * 16 + kk) * SA_STRIDE + j];
        dst[(g * 4 + 0) * 4] = a.x;
        dst[(g * 4 + 1) * 4] = a.y;
        dst[(g * 4 + 2) * 4] = a.z;
        dst[(g * 4 + 3) * 4] = a.w;
    }
    cp_async_wait_all();
    __syncthreads();

    const int wid = tid >> 5, lane = tid & 31;
    const int mg = wid >> 1, nh = wid & 1;
    #pragma unroll
    for (int nf = 0; nf < 8; nf++)
        acc[nf][0] = acc[nf][1] = acc[nf][2] = acc[nf][3] = 0.f;

    #pragma unroll
    for (int kk = 0; kk < 16; kk++) {
        uint32_t au[4];
        float4 av = *(const float4*)&sA[(mg * 16 + kk) * SA_STRIDE + lane * 4];
        au[0] = __float_as_uint(av.x); au[1] = __float_as_uint(av.y);
        au[2] = __float_as_uint(av.z); au[3] = __float_as_uint(av.w);
        #pragma unroll
        for (int nf = 0; nf < 8; nf++) {
            uint32_t bu[2];
            float2 bv = *(const float2*)&sW[((nh * 8 + nf) * 16 + kk) * 64 + lane * 2];
            bu[0] = __float_as_uint(bv.x); bu[1] = __float_as_uint(bv.y);
            mma_tf32(acc[nf], au, bu);
        }
    }
    __syncthreads();
}

// ---------------- 2: hW(fp16) = x @ W1' + b1p  (BN1 folded into W1') ------------
__global__ void __launch_bounds__(256, 2)
gemm128_a(const float* __restrict__ A, const float* __restrict__ Wp,
          const float* __restrict__ bias, __half2* __restrict__ Ch, int n)
{
    extern __shared__ float sh[];
    float* sW = sh;
    float* sA = sh + SW_FLOATS;
    const int tid = threadIdx.x;
    const int r0  = blockIdx.x * TM;

    float acc[8][4];
    gemm_mma_core_f32(sW, sA, A, Wp, r0, n, tid, acc);

    const int wid = tid >> 5, lane = tid & 31;
    const int mg = wid >> 1, nh = wid & 1;
    const int g = lane >> 2, c = lane & 3;
    int r_lo = r0 + mg * 16 + g;
    #pragma unroll
    for (int nf = 0; nf < 8; nf++) {
        int col = nh * 64 + nf * 8 + c * 2;
        float2 bp = *(const float2*)&bias[col];
        if (r_lo < n)
            Ch[r_lo * 64 + (col >> 1)] =
                __floats2half2_rn(acc[nf][0] + bp.x, acc[nf][1] + bp.y);
        if (r_lo + 8 < n)
            Ch[(r_lo + 8) * 64 + (col >> 1)] =
                __floats2half2_rn(acc[nf][2] + bp.x, acc[nf][3] + bp.y);
    }
}

// ---------------- 3: y1 = tanh(A @ hW + b1), ALSO computes g_ev -----------------
// hW gathered in fp16 (256B/row), accumulate fp32, 4-deep gather pipeline.
__global__ void spmm_tanh(const uint2* __restrict__ Hh, const int* __restrict__ cols,
                          const float* __restrict__ vals, const int* __restrict__ rel,
                          const float* __restrict__ relc, const float* __restrict__ b1,
                          float* __restrict__ y1f, uint2* __restrict__ y1h, int n)
{
    int w = (blockIdx.x * blockDim.x + threadIdx.x) >> 5;
    int lane = threadIdx.x & 31;
    if (w >= n) return;
    int s = g_rowptr[w], e = g_rowptr[w + 1];
    float4 acc = make_float4(0.f, 0.f, 0.f, 0.f);
    for (int base = s; base < e; base += 32) {
        int idx = base + lane;
        int   cl = 0; float vl = 0.f;
        if (idx < e) {
            cl = __ldg(&cols[idx]);
            vl = __ldg(&vals[idx]);
            g_ev[idx] = vl / (__ldg(&relc[__ldg(&rel[idx])]) + 1.f);
        }
        int m = min(32, e - base);
        int j = 0;
        for (; j + 4 <= m; j += 4) {
            int   c0 = __shfl_sync(0xffffffffu, cl, j);
            int   c1 = __shfl_sync(0xffffffffu, cl, j + 1);
            int   c2 = __shfl_sync(0xffffffffu, cl, j + 2);
            int   c3 = __shfl_sync(0xffffffffu, cl, j + 3);
            float v0 = __shfl_sync(0xffffffffu, vl, j);
            float v1 = __shfl_sync(0xffffffffu, vl, j + 1);
            float v2 = __shfl_sync(0xffffffffu, vl, j + 2);
            float v3 = __shfl_sync(0xffffffffu, vl, j + 3);
            float4 h0 = h2f4(Hh[c0 * 32 + lane]);
            float4 h1 = h2f4(Hh[c1 * 32 + lane]);
            float4 h2 = h2f4(Hh[c2 * 32 + lane]);
            float4 h3 = h2f4(Hh[c3 * 32 + lane]);
            acc.x += v0 * h0.x + v1 * h1.x + v2 * h2.x + v3 * h3.x;
            acc.y += v0 * h0.y + v1 * h1.y + v2 * h2.y + v3 * h3.y;
            acc.z += v0 * h0.z + v1 * h1.z + v2 * h2.z + v3 * h3.z;
            acc.w += v0 * h0.w + v1 * h1.w + v2 * h2.w + v3 * h3.w;
        }
        for (; j < m; j++) {
            int   c = __shfl_sync(0xffffffffu, cl, j);
            float v = __shfl_sync(0xffffffffu, vl, j);
            float4 h = h2f4(Hh[c * 32 + lane]);
            acc.x += v * h.x; acc.y += v * h.y; acc.z += v * h.z; acc.w += v * h.w;
        }
    }
    float4 b = ((const float4*)b1)[lane];
    float4 o = make_float4(tanhf(acc.x + b.x), tanhf(acc.y + b.y),
                           tanhf(acc.z + b.z), tanhf(acc.w + b.w));
    ((float4*)y1f)[w * 32 + lane] = o;
    uint2 oh;
    *reinterpret_cast<__half2*>(&oh.x) = __floats2half2_rn(o.x, o.y);
    *reinterpret_cast<__half2*>(&oh.y) = __floats2half2_rn(o.z, o.w);
    y1h[w * 32 + lane] = oh;
}

// ---------------- 4: z(fp16) = A_rel @ BN2(y1) + BN2(y1)*(ck+1) -----------------
__global__ void spmm_rgin(const float* __restrict__ y1f, const uint2* __restrict__ Yh,
                          const int* __restrict__ cols, const float* __restrict__ ev,
                          const float* __restrict__ ck, uint2* __restrict__ zh, int n)
{
    int w = (blockIdx.x * blockDim.x + threadIdx.x) >> 5;
    int lane = threadIdx.x & 31;
    if (w >= n) return;
    int s = g_rowptr[w], e = g_rowptr[w + 1];
    float4 accA = make_float4(0.f, 0.f, 0.f, 0.f);
    float  accB = 0.f;
    for (int base = s; base < e; base += 32) {
        int idx = base + lane;
        int cl = 0; float el = 0.f;
        if (idx < e) { cl = __ldg(&cols[idx]); el = __ldg(&ev[idx]); }
        int m = min(32, e - base);
        int j = 0;
        for (; j + 4 <= m; j += 4) {
            int   c0 = __shfl_sync(0xffffffffu, cl, j);
            int   c1 = __shfl_sync(0xffffffffu, cl, j + 1);
            int   c2 = __shfl_sync(0xffffffffu, cl, j + 2);
            int   c3 = __shfl_sync(0xffffffffu, cl, j + 3);
            float e0 = __shfl_sync(0xffffffffu, el, j);
            float e1 = __shfl_sync(0xffffffffu, el, j + 1);
            float e2 = __shfl_sync(0xffffffffu, el, j + 2);
            float e3 = __shfl_sync(0xffffffffu, el, j + 3);
            float4 h0 = h2f4(Yh[c0 * 32 + lane]);
            float4 h1 = h2f4(Yh[c1 * 32 + lane]);
            float4 h2 = h2f4(Yh[c2 * 32 + lane]);
            float4 h3 = h2f4(Yh[c3 * 32 + lane]);
            accA.x += e0 * h0.x + e1 * h1.x + e2 * h2.x + e3 * h3.x;
            accA.y += e0 * h0.y + e1 * h1.y + e2 * h2.y + e3 * h3.y;
            accA.z += e0 * h0.z + e1 * h1.z + e2 * h2.z + e3 * h3.z;
            accA.w += e0 * h0.w + e1 * h1.w + e2 * h2.w + e3 * h3.w;
            accB += e0 + e1 + e2 + e3;
        }
        for (; j < m; j++) {
            int   c  = __shfl_sync(0xffffffffu, cl, j);
            float ee = __shfl_sync(0xffffffffu, el, j);
            float4 h = h2f4(Yh[c * 32 + lane]);
            accA.x += ee * h.x; accA.y += ee * h.y;
            accA.z += ee * h.z; accA.w += ee * h.w;
            accB += ee;
        }
    }
    int d = lane * 4;
    float4 s2 = *(const float4*)&g_s2[d];
    float4 t2 = *(const float4*)&g_t2[d];
    float4 yr = ((const float4*)y1f)[w * 32 + lane];   // self-term in fp32
    float  cm = __ldg(&ck[w]) + 1.f;
    float4 o;
    o.x = s2.x * accA.x + t2.x * accB + (yr.x * s2.x + t2.x) * cm;
    o.y = s2.y * accA.y + t2.y * accB + (yr.y * s2.y + t2.y) * cm;
    o.z = s2.z * accA.z + t2.z * accB + (yr.z * s2.z + t2.z) * cm;
    o.w = s2.w * accA.w + t2.w * accB + (yr.w * s2.w + t2.w) * cm;
    uint2 oh;
    *reinterpret_cast<__half2*>(&oh.x) = __floats2half2_rn(o.x, o.y);
    *reinterpret_cast<__half2*>(&oh.y) = __floats2half2_rn(o.z, o.w);
    zh[w * 32 + lane] = oh;
}

// -------- 5: gemm2 (z @ Wd' + bd) FUSED with final l2-normalize-concat ----------
__global__ void __launch_bounds__(256, 2)
gemm128_norm(const uint2* __restrict__ Ah, const float* __restrict__ Wp,
             const float* __restrict__ bias,
             const float* __restrict__ x, const float* __restrict__ y1,
             float* __restrict__ out, int n)
{
    extern __shared__ float sh[];
    float* sW = sh;
    float* sA = sh + SW_FLOATS;
    const int tid = threadIdx.x;
    const int r0  = blockIdx.x * TM;

    float acc[8][4];
    gemm_mma_core_f16(sW, sA, Ah, Wp, r0, n, tid, acc);

    const int wid = tid >> 5, lane = tid & 31;
    const int mg = wid >> 1, nh = wid & 1;
    const int g = lane >> 2, c = lane & 3;
    #pragma unroll
    for (int nf = 0; nf < 8; nf++) {
        int col = nh * 64 + nf * 8 + c * 2;
        int lr = mg * 16 + g;
        *(float2*)&sA[lr * SA_STRIDE + col]       = make_float2(acc[nf][0], acc[nf][1]);
        *(float2*)&sA[(lr + 8) * SA_STRIDE + col] = make_float2(acc[nf][2], acc[nf][3]);
    }
    __syncthreads();

    float4 bv = ((const float4*)bias)[lane];
    #pragma unroll
    for (int rr = 0; rr < 8; rr++) {
        int row = wid * 8 + rr;
        int gr  = r0 + row;
        if (gr >= n) continue;
        float4 cc = *(float4*)&sA[row * SA_STRIDE + lane * 4];
        cc.x += bv.x; cc.y += bv.y; cc.z += bv.z; cc.w += bv.w;
        float4 a = ((const float4*)x )[gr * 32 + lane];
        float4 b = ((const float4*)y1)[gr * 32 + lane];
        float sa = a.x*a.x + a.y*a.y + a.z*a.z + a.w*a.w;
        float sb = b.x*b.x + b.y*b.y + b.z*b.z + b.w*b.w;
        float sc = cc.x*cc.x + cc.y*cc.y + cc.z*cc.z + cc.w*cc.w;
        #pragma unroll
        for (int o = 16; o; o >>= 1) {
            sa += __shfl_xor_sync(0xffffffffu, sa, o);
            sb += __shfl_xor_sync(0xffffffffu, sb, o);
            sc += __shfl_xor_sync(0xffffffffu, sc, o);
        }
        float ra = rsqrtf(fmaxf(sa, 1e-12f));
        float rb = rsqrtf(fmaxf(sb, 1e-12f));
        float rc = rsqrtf(fmaxf(sc, 1e-12f));
        float na = sa * ra * ra, nb = sb * rb * rb, nc = sc * rc * rc;
        float rt = rsqrtf(fmaxf(na + nb + nc, 1e-12f));
        float fa = ra * rt, fb = rb * rt, fc = rc * rt;
        float4* O = (float4*)out;
        int obase = gr * 96;
        O[obase + lane]      = make_float4(a.x*fa, a.y*fa, a.z*fa, a.w*fa);
        O[obase + 32 + lane] = make_float4(b.x*fb, b.y*fb, b.z*fb, b.w*fb);
        O[obase + 64 + lane] = make_float4(cc.x*fc, cc.y*fc, cc.z*fc, cc.w*fc);
    }
}

// ---------------- launch --------------------------------------------------------
extern "C" void kernel_launch(void* const* d_in, const int* in_sizes, int n_in,
                              void* d_out, int out_size)
{
    const float* x      = (const float*)d_in[0];
    const int*   rows   = (const int*)  d_in[1];
    const int*   cols   = (const int*)  d_in[2];
    const float* adj    = (const float*)d_in[3];
    const int*   rel    = (const int*)  d_in[4];
    const float* gamma1 = (const float*)d_in[5];
    const float* beta1  = (const float*)d_in[6];
    const float* mean1  = (const float*)d_in[7];
    const float* var1   = (const float*)d_in[8];
    const float* W1     = (const float*)d_in[9];
    const float* b1     = (const float*)d_in[10];
    const float* gamma2 = (const float*)d_in[11];
    const float* beta2  = (const float*)d_in[12];
    const float* mean2  = (const float*)d_in[13];
    const float* var2   = (const float*)d_in[14];
    const float* relc   = (const float*)d_in[15];
    const float* ck     = (const float*)d_in[16];
    const float* Wd     = (const float*)d_in[17];
    const float* bd     = (const float*)d_in[18];
    float* out = (float*)d_out;

    const int n = in_sizes[0] / DIM;     // 50000
    const int e = in_sizes[1];           // 640000

    cudaFuncSetAttribute(gemm128_a,    cudaFuncAttributeMaxDynamicSharedMemorySize, GEMM_SMEM);
    cudaFuncSetAttribute(gemm128_norm, cudaFuncAttributeMaxDynamicSharedMemorySize, GEMM_SMEM);

    // __device__ symbols are NOT valid host-side pointers — fetch device addresses.
    float *y1, *ev, *Wp1, *Wpd, *b1p;
    uint2 *hWh, *y1h, *zh;
    cudaGetSymbolAddress((void**)&hWh, g_hWh);
    cudaGetSymbolAddress((void**)&y1,  g_y1);
    cudaGetSymbolAddress((void**)&y1h, g_y1h);
    cudaGetSymbolAddress((void**)&zh,  g_zh);
    cudaGetSymbolAddress((void**)&ev,  g_ev);
    cudaGetSymbolAddress((void**)&Wp1, g_Wp1);
    cudaGetSymbolAddress((void**)&Wpd, g_Wpd);
    cudaGetSymbolAddress((void**)&b1p, g_b1p);

    int prep_threads = (n + 1 > SW_FLOATS) ? n + 1 : SW_FLOATS;
    prep_all<<<(prep_threads + 255) / 256, 256>>>(gamma1, beta1, mean1, var1,
                                                  gamma2, beta2, mean2, var2,
                                                  W1, Wd, rows, n, e);

    int gemm_blocks = (n + TM - 1) / TM;
    gemm128_a<<<gemm_blocks, 256, GEMM_SMEM>>>(x, Wp1, b1p, (__half2*)hWh, n);

    int warp_blocks = (n * 32 + 255) / 256;
    spmm_tanh<<<warp_blocks, 256>>>(hWh, cols, adj, rel, relc, b1, y1, y1h, n);
    spmm_rgin<<<warp_blocks, 256>>>(y1, y1h, cols, ev, ck, zh, n);

    gemm128_norm<<<gemm_blocks, 256, GEMM_SMEM>>>(zh, Wpd, bd, x, y1, out, n);
}

// round 16
// speedup vs baseline: 1.0876x; 1.0260x over previous
#include <cuda_runtime.h>
#include <cuda_fp16.h>
#include <mma.h>
#include <math.h>
#include <cstdint>

using namespace nvcuda;

// Problem constants (fixed by the dataset)
#define N_NODES 50000
#define DIM     128
#define N_EDGES 640000

// GEMM: block = 256 thr (8 warps), tile 64 rows x 128 cols, raw mma.m16n8k8.tf32
#define TM 64
#define SW_FLOATS 16384                   // W fragment-ordered: [16 nf][16 kk][32 lane][2]
#define SA_STRIDE 132                     // kk-stride in floats (128 + 4 pad)
#define SA_FLOATS (64 * SA_STRIDE)
#define GEMM_SMEM ((SW_FLOATS + SA_FLOATS) * 4)   // 99328 B -> 2 blocks/SM

// ---------------- scratch (device globals; no allocation allowed) ----------------
__device__ uint2 g_hWh[N_NODES*32];       // hW in fp16 (gather table; 256B/row)
__device__ uint2 g_y1h[N_NODES*32];       // y1 in fp16 (gathers + self-term + concat)
__device__ uint2 g_zh [N_NODES*32];       // z in fp16 (only consumed by tf32 GEMM)
__device__ float g_ev [N_EDGES];
__device__ float g_Wp1[SW_FLOATS];        // W1 (BN1-folded, tf32) in B-fragment order
__device__ float g_Wpd[SW_FLOATS];        // Wd (tf32) in B-fragment order
__device__ float g_b1p[DIM];              // bias from BN1 shift: sum_k t1[k]*W1[k][n]
__device__ int   g_rowptr[N_NODES+1];
__device__ float g_s2[DIM], g_t2[DIM];

__device__ __forceinline__ void cp_async16(uint32_t smem_addr, const void* gptr) {
    asm volatile("cp.async.cg.shared.global [%0], [%1], 16;\n"
                 :: "r"(smem_addr), "l"(gptr) : "memory");
}
__device__ __forceinline__ void cp_async_commit() {
    asm volatile("cp.async.commit_group;\n" ::: "memory");
}
__device__ __forceinline__ void cp_async_wait_all() {
    asm volatile("cp.async.wait_group 0;\n" ::: "memory");
}

__device__ __forceinline__ void mma_tf32(float acc[4], const uint32_t a[4], const uint32_t b[2]) {
    asm volatile("mma.sync.aligned.m16n8k8.row.col.f32.tf32.tf32.f32 "
                 "{%0,%1,%2,%3}, {%4,%5,%6,%7}, {%8,%9}, {%0,%1,%2,%3};"
                 : "+f"(acc[0]), "+f"(acc[1]), "+f"(acc[2]), "+f"(acc[3])
                 : "r"(a[0]), "r"(a[1]), "r"(a[2]), "r"(a[3]), "r"(b[0]), "r"(b[1]));
}

__device__ __forceinline__ float4 h2f4(uint2 h) {
    float2 a = __half22float2(*reinterpret_cast<__half2*>(&h.x));
    float2 b = __half22float2(*reinterpret_cast<__half2*>(&h.y));
    return make_float4(a.x, a.y, b.x, b.y);
}

// ---------------- 1: fused prep: BN fold + W permute + bias fold + rowptr -------
__global__ void prep_all(const float* __restrict__ g1, const float* __restrict__ b1,
                         const float* __restrict__ m1, const float* __restrict__ v1,
                         const float* __restrict__ g2, const float* __restrict__ b2,
                         const float* __restrict__ m2, const float* __restrict__ v2,
                         const float* __restrict__ W1, const float* __restrict__ Wd,
                         const int* __restrict__ rows, int n, int e)
{
    int i = blockIdx.x * blockDim.x + threadIdx.x;

    if (i < DIM) {
        float s2 = g2[i] * rsqrtf(v2[i] + 1e-3f);
        g_s2[i] = s2; g_t2[i] = b2[i] - m2[i] * s2;
        float s = 0.f;
        for (int k = 0; k < DIM; k++) {
            float s1k = g1[k] * rsqrtf(v1[k] + 1e-3f);
            float t1k = b1[k] - m1[k] * s1k;
            s += t1k * W1[k * DIM + i];
        }
        g_b1p[i] = s;
    }
    if (i < SW_FLOATS) {
        int t    = i & 1;
        int lane = (i >> 1) & 31;
        int kk   = (i >> 6) & 15;
        int nf   = i >> 10;
        int k  = kk * 8 + (lane & 3) + 4 * t;
        int nn = nf * 8 + (lane >> 2);
        float s1k = g1[k] * rsqrtf(v1[k] + 1e-3f);
        g_Wp1[i] = wmma::__float_to_tf32(s1k * W1[k * DIM + nn]);
        g_Wpd[i] = wmma::__float_to_tf32(Wd[k * DIM + nn]);
    }
    if (i <= n) {
        int lo = 0, hi = e;
        while (lo < hi) {
            int mid = (lo + hi) >> 1;
            if (rows[mid] < i) lo = mid + 1; else hi = mid;
        }
        g_rowptr[i] = lo;
    }
}

// ----- GEMM core (fp32 A): fragment-ordered smem, raw mma; fills acc[8][4] ------
__device__ __forceinline__ void gemm_mma_core_f32(
    float* sW, float* sA,
    const float* __restrict__ A, const float* __restrict__ Wp,
    int r0, int n, int tid, float acc[8][4])
{
    uint32_t swb = (uint32_t)__cvta_generic_to_shared(sW);
    const float4* W4 = (const float4*)Wp;
    #pragma unroll
    for (int k = 0; k < 16; k++) {
        int idx = tid + k * 256;
        cp_async16(swb + idx * 16, W4 + idx);
    }
    cp_async_commit();

    #pragma unroll
    for (int k = 0; k < 8; k++) {
        int idx = tid + k * 256;
        int row = idx >> 5, q = idx & 31;
        int gr = r0 + row;
        float4 a = make_float4(0.f, 0.f, 0.f, 0.f);
        if (gr < n) a = ((const float4*)A)[gr * 32 + q];
        a.x = wmma::__float_to_tf32(a.x);
        a.y = wmma::__float_to_tf32(a.y);
        a.z = wmma::__float_to_tf32(a.z);
        a.w = wmma::__float_to_tf32(a.w);
        int mg = row >> 4, g = row & 7, jr = (row >> 3) & 1;
        int kk = q >> 1, j = (q & 1) * 2 + jr;
        float* dst = &sA[(mg * 16 + kk) * SA_STRIDE + j];
        dst[(g * 4 + 0) * 4] = a.x;
        dst[(g * 4 + 1) * 4] = a.y;
        dst[(g * 4 + 2) * 4] = a.z;
        dst[(g * 4 + 3) * 4] = a.w;
    }
    cp_async_wait_all();
    __syncthreads();

    const int wid = tid >> 5, lane = tid & 31;
    const int mg = wid >> 1, nh = wid & 1;
    #pragma unroll
    for (int nf = 0; nf < 8; nf++)
        acc[nf][0] = acc[nf][1] = acc[nf][2] = acc[nf][3] = 0.f;

    #pragma unroll
    for (int kk = 0; kk < 16; kk++) {
        uint32_t au[4];
        float4 av = *(const float4*)&sA[(mg * 16 + kk) * SA_STRIDE + lane * 4];
        au[0] = __float_as_uint(av.x); au[1] = __float_as_uint(av.y);
        au[2] = __float_as_uint(av.z); au[3] = __float_as_uint(av.w);
        #pragma unroll
        for (int nf = 0; nf < 8; nf++) {
            uint32_t bu[2];
            float2 bv = *(const float2*)&sW[((nh * 8 + nf) * 16 + kk) * 64 + lane * 2];
            bu[0] = __float_as_uint(bv.x); bu[1] = __float_as_uint(bv.y);
            mma_tf32(acc[nf], au, bu);
        }
    }
    __syncthreads();
}

// ----- GEMM core (fp16 A source): same, but A is uint2/half2 rows ---------------
__device__ __forceinline__ void gemm_mma_core_f16(
    float* sW, float* sA,
    const uint2* __restrict__ Ah, const float* __restrict__ Wp,
    int r0, int n, int tid, float acc[8][4])
{
    uint32_t swb = (uint32_t)__cvta_generic_to_shared(sW);
    const float4* W4 = (const float4*)Wp;
    #pragma unroll
    for (int k = 0; k < 16; k++) {
        int idx = tid + k * 256;
        cp_async16(swb + idx * 16, W4 + idx);
    }
    cp_async_commit();

    #pragma unroll
    for (int k = 0; k < 8; k++) {
        int idx = tid + k * 256;
        int row = idx >> 5, q = idx & 31;
        int gr = r0 + row;
        float4 a = make_float4(0.f, 0.f, 0.f, 0.f);
        if (gr < n) a = h2f4(Ah[gr * 32 + q]);   // fp16 -> fp32 exact; tf32 round below
        a.x = wmma::__float_to_tf32(a.x);
        a.y = wmma::__float_to_tf32(a.y);
        a.z = wmma::__float_to_tf32(a.z);
        a.w = wmma::__float_to_tf32(a.w);
        int mg = row >> 4, g = row & 7, jr = (row >> 3) & 1;
        int kk = q >> 1, j = (q & 1) * 2 + jr;
        float* dst = &sA[(mg * 16 + kk) * SA_STRIDE + j];
        dst[(g * 4 + 0) * 4] = a.x;
        dst[(g * 4 + 1) * 4] = a.y;
        dst[(g * 4 + 2) * 4] = a.z;
        dst[(g * 4 + 3) * 4] = a.w;
    }
    cp_async_wait_all();
    __syncthreads();

    const int wid = tid >> 5, lane = tid & 31;
    const int mg = wid >> 1, nh = wid & 1;
    #pragma unroll
    for (int nf = 0; nf < 8; nf++)
        acc[nf][0] = acc[nf][1] = acc[nf][2] = acc[nf][3] = 0.f;

    #pragma unroll
    for (int kk = 0; kk < 16; kk++) {
        uint32_t au[4];
        float4 av = *(const float4*)&sA[(mg * 16 + kk) * SA_STRIDE + lane * 4];
        au[0] = __float_as_uint(av.x); au[1] = __float_as_uint(av.y);
        au[2] = __float_as_uint(av.z); au[3] = __float_as_uint(av.w);
        #pragma unroll
        for (int nf = 0; nf < 8; nf++) {
            uint32_t bu[2];
            float2 bv = *(const float2*)&sW[((nh * 8 + nf) * 16 + kk) * 64 + lane * 2];
            bu[0] = __float_as_uint(bv.x); bu[1] = __float_as_uint(bv.y);
            mma_tf32(acc[nf], au, bu);
        }
    }
    __syncthreads();
}

// ---------------- 2: hW(fp16) = x @ W1' + b1p  (BN1 folded into W1') ------------
__global__ void __launch_bounds__(256, 2)
gemm128_a(const float* __restrict__ A, const float* __restrict__ Wp,
          const float* __restrict__ bias, __half2* __restrict__ Ch, int n)
{
    extern __shared__ float sh[];
    float* sW = sh;
    float* sA = sh + SW_FLOATS;
    const int tid = threadIdx.x;
    const int r0  = blockIdx.x * TM;

    float acc[8][4];
    gemm_mma_core_f32(sW, sA, A, Wp, r0, n, tid, acc);

    const int wid = tid >> 5, lane = tid & 31;
    const int mg = wid >> 1, nh = wid & 1;
    const int g = lane >> 2, c = lane & 3;
    int r_lo = r0 + mg * 16 + g;
    #pragma unroll
    for (int nf = 0; nf < 8; nf++) {
        int col = nh * 64 + nf * 8 + c * 2;
        float2 bp = *(const float2*)&bias[col];
        if (r_lo < n)
            Ch[r_lo * 64 + (col >> 1)] =
                __floats2half2_rn(acc[nf][0] + bp.x, acc[nf][1] + bp.y);
        if (r_lo + 8 < n)
            Ch[(r_lo + 8) * 64 + (col >> 1)] =
                __floats2half2_rn(acc[nf][2] + bp.x, acc[nf][3] + bp.y);
    }
}

// ---------------- 3: y1(fp16) = tanh(A @ hW + b1), ALSO computes g_ev -----------
// hW gathered in fp16 (256B/row), accumulate fp32, 4-deep gather pipeline.
__global__ void spmm_tanh(const uint2* __restrict__ Hh, const int* __restrict__ cols,
                          const float* __restrict__ vals, const int* __restrict__ rel,
                          const float* __restrict__ relc, const float* __restrict__ b1,
                          uint2* __restrict__ y1h, int n)
{
    int w = (blockIdx.x * blockDim.x + threadIdx.x) >> 5;
    int lane = threadIdx.x & 31;
    if (w >= n) return;
    int s = g_rowptr[w], e = g_rowptr[w + 1];
    float4 acc = make_float4(0.f, 0.f, 0.f, 0.f);
    for (int base = s; base < e; base += 32) {
        int idx = base + lane;
        int   cl = 0; float vl = 0.f;
        if (idx < e) {
            cl = __ldg(&cols[idx]);
            vl = __ldg(&vals[idx]);
            g_ev[idx] = vl / (__ldg(&relc[__ldg(&rel[idx])]) + 1.f);
        }
        int m = min(32, e - base);
        int j = 0;
        for (; j + 4 <= m; j += 4) {
            int   c0 = __shfl_sync(0xffffffffu, cl, j);
            int   c1 = __shfl_sync(0xffffffffu, cl, j + 1);
            int   c2 = __shfl_sync(0xffffffffu, cl, j + 2);
            int   c3 = __shfl_sync(0xffffffffu, cl, j + 3);
            float v0 = __shfl_sync(0xffffffffu, vl, j);
            float v1 = __shfl_sync(0xffffffffu, vl, j + 1);
            float v2 = __shfl_sync(0xffffffffu, vl, j + 2);
            float v3 = __shfl_sync(0xffffffffu, vl, j + 3);
            float4 h0 = h2f4(Hh[c0 * 32 + lane]);
            float4 h1 = h2f4(Hh[c1 * 32 + lane]);
            float4 h2 = h2f4(Hh[c2 * 32 + lane]);
            float4 h3 = h2f4(Hh[c3 * 32 + lane]);
            acc.x += v0 * h0.x + v1 * h1.x + v2 * h2.x + v3 * h3.x;
            acc.y += v0 * h0.y + v1 * h1.y + v2 * h2.y + v3 * h3.y;
            acc.z += v0 * h0.z + v1 * h1.z + v2 * h2.z + v3 * h3.z;
            acc.w += v0 * h0.w + v1 * h1.w + v2 * h2.w + v3 * h3.w;
        }
        for (; j < m; j++) {
            int   c = __shfl_sync(0xffffffffu, cl, j);
            float v = __shfl_sync(0xffffffffu, vl, j);
            float4 h = h2f4(Hh[c * 32 + lane]);
            acc.x += v * h.x; acc.y += v * h.y; acc.z += v * h.z; acc.w += v * h.w;
        }
    }
    float4 b = ((const float4*)b1)[lane];
    float4 o = make_float4(tanhf(acc.x + b.x), tanhf(acc.y + b.y),
                           tanhf(acc.z + b.z), tanhf(acc.w + b.w));
    uint2 oh;
    *reinterpret_cast<__half2*>(&oh.x) = __floats2half2_rn(o.x, o.y);
    *reinterpret_cast<__half2*>(&oh.y) = __floats2half2_rn(o.z, o.w);
    y1h[w * 32 + lane] = oh;
}

// ---------------- 4: z(fp16) = A_rel @ BN2(y1) + BN2(y1)*(ck+1) -----------------
__global__ void spmm_rgin(const uint2* __restrict__ Yh,
                          const int* __restrict__ cols, const float* __restrict__ ev,
                          const float* __restrict__ ck, uint2* __restrict__ zh, int n)
{
    int w = (blockIdx.x * blockDim.x + threadIdx.x) >> 5;
    int lane = threadIdx.x & 31;
    if (w >= n) return;
    int s = g_rowptr[w], e = g_rowptr[w + 1];
    float4 accA = make_float4(0.f, 0.f, 0.f, 0.f);
    float  accB = 0.f;
    for (int base = s; base < e; base += 32) {
        int idx = base + lane;
        int cl = 0; float el = 0.f;
        if (idx < e) { cl = __ldg(&cols[idx]); el = __ldg(&ev[idx]); }
        int m = min(32, e - base);
        int j = 0;
        for (; j + 4 <= m; j += 4) {
            int   c0 = __shfl_sync(0xffffffffu, cl, j);
            int   c1 = __shfl_sync(0xffffffffu, cl, j + 1);
            int   c2 = __shfl_sync(0xffffffffu, cl, j + 2);
            int   c3 = __shfl_sync(0xffffffffu, cl, j + 3);
            float e0 = __shfl_sync(0xffffffffu, el, j);
            float e1 = __shfl_sync(0xffffffffu, el, j + 1);
            float e2 = __shfl_sync(0xffffffffu, el, j + 2);
            float e3 = __shfl_sync(0xffffffffu, el, j + 3);
            float4 h0 = h2f4(Yh[c0 * 32 + lane]);
            float4 h1 = h2f4(Yh[c1 * 32 + lane]);
            float4 h2 = h2f4(Yh[c2 * 32 + lane]);
            float4 h3 = h2f4(Yh[c3 * 32 + lane]);
            accA.x += e0 * h0.x + e1 * h1.x + e2 * h2.x + e3 * h3.x;
            accA.y += e0 * h0.y + e1 * h1.y + e2 * h2.y + e3 * h3.y;
            accA.z += e0 * h0.z + e1 * h1.z + e2 * h2.z + e3 * h3.z;
            accA.w += e0 * h0.w + e1 * h1.w + e2 * h2.w + e3 * h3.w;
            accB += e0 + e1 + e2 + e3;
        }
        for (; j < m; j++) {
            int   c  = __shfl_sync(0xffffffffu, cl, j);
            float ee = __shfl_sync(0xffffffffu, el, j);
            float4 h = h2f4(Yh[c * 32 + lane]);
            accA.x += ee * h.x; accA.y += ee * h.y;
            accA.z += ee * h.z; accA.w += ee * h.w;
            accB += ee;
        }
    }
    int d = lane * 4;
    float4 s2 = *(const float4*)&g_s2[d];
    float4 t2 = *(const float4*)&g_t2[d];
    float4 yr = h2f4(Yh[w * 32 + lane]);   // self-term (fp16->fp32 exact)
    float  cm = __ldg(&ck[w]) + 1.f;
    float4 o;
    o.x = s2.x * accA.x + t2.x * accB + (yr.x * s2.x + t2.x) * cm;
    o.y = s2.y * accA.y + t2.y * accB + (yr.y * s2.y + t2.y) * cm;
    o.z = s2.z * accA.z + t2.z * accB + (yr.z * s2.z + t2.z) * cm;
    o.w = s2.w * accA.w + t2.w * accB + (yr.w * s2.w + t2.w) * cm;
    uint2 oh;
    *reinterpret_cast<__half2*>(&oh.x) = __floats2half2_rn(o.x, o.y);
    *reinterpret_cast<__half2*>(&oh.y) = __floats2half2_rn(o.z, o.w);
    zh[w * 32 + lane] = oh;
}

// -------- 5: gemm2 (z @ Wd' + bd) FUSED with final l2-normalize-concat ----------
__global__ void __launch_bounds__(256, 2)
gemm128_norm(const uint2* __restrict__ Ah, const float* __restrict__ Wp,
             const float* __restrict__ bias,
             const float* __restrict__ x, const uint2* __restrict__ y1h,
             float* __restrict__ out, int n)
{
    extern __shared__ float sh[];
    float* sW = sh;
    float* sA = sh + SW_FLOATS;
    const int tid = threadIdx.x;
    const int r0  = blockIdx.x * TM;

    float acc[8][4];
    gemm_mma_core_f16(sW, sA, Ah, Wp, r0, n, tid, acc);

    const int wid = tid >> 5, lane = tid & 31;
    const int mg = wid >> 1, nh = wid & 1;
    const int g = lane >> 2, c = lane & 3;
    #pragma unroll
    for (int nf = 0; nf < 8; nf++) {
        int col = nh * 64 + nf * 8 + c * 2;
        int lr = mg * 16 + g;
        *(float2*)&sA[lr * SA_STRIDE + col]       = make_float2(acc[nf][0], acc[nf][1]);
        *(float2*)&sA[(lr + 8) * SA_STRIDE + col] = make_float2(acc[nf][2], acc[nf][3]);
    }
    __syncthreads();

    float4 bv = ((const float4*)bias)[lane];
    #pragma unroll
    for (int rr = 0; rr < 8; rr++) {
        int row = wid * 8 + rr;
        int gr  = r0 + row;
        if (gr >= n) continue;
        float4 cc = *(float4*)&sA[row * SA_STRIDE + lane * 4];
        cc.x += bv.x; cc.y += bv.y; cc.z += bv.z; cc.w += bv.w;
        float4 a = ((const float4*)x)[gr * 32 + lane];
        float4 b = h2f4(y1h[gr * 32 + lane]);    // fp16 y1 (exact conversion)
        float sa = a.x*a.x + a.y*a.y + a.z*a.z + a.w*a.w;
        float sb = b.x*b.x + b.y*b.y + b.z*b.z + b.w*b.w;
        float sc = cc.x*cc.x + cc.y*cc.y + cc.z*cc.z + cc.w*cc.w;
        #pragma unroll
        for (int o = 16; o; o >>= 1) {
            sa += __shfl_xor_sync(0xffffffffu, sa, o);
            sb += __shfl_xor_sync(0xffffffffu, sb, o);
            sc += __shfl_xor_sync(0xffffffffu, sc, o);
        }
        float ra = rsqrtf(fmaxf(sa, 1e-12f));
        float rb = rsqrtf(fmaxf(sb, 1e-12f));
        float rc = rsqrtf(fmaxf(sc, 1e-12f));
        float na = sa * ra * ra, nb = sb * rb * rb, nc = sc * rc * rc;
        float rt = rsqrtf(fmaxf(na + nb + nc, 1e-12f));
        float fa = ra * rt, fb = rb * rt, fc = rc * rt;
        float4* O = (float4*)out;
        int obase = gr * 96;
        O[obase + lane]      = make_float4(a.x*fa, a.y*fa, a.z*fa, a.w*fa);
        O[obase + 32 + lane] = make_float4(b.x*fb, b.y*fb, b.z*fb, b.w*fb);
        O[obase + 64 + lane] = make_float4(cc.x*fc, cc.y*fc, cc.z*fc, cc.w*fc);
    }
}

// ---------------- launch --------------------------------------------------------
extern "C" void kernel_launch(void* const* d_in, const int* in_sizes, int n_in,
                              void* d_out, int out_size)
{
    const float* x      = (const float*)d_in[0];
    const int*   rows   = (const int*)  d_in[1];
    const int*   cols   = (const int*)  d_in[2];
    const float* adj    = (const float*)d_in[3];
    const int*   rel    = (const int*)  d_in[4];
    const float* gamma1 = (const float*)d_in[5];
    const float* beta1  = (const float*)d_in[6];
    const float* mean1  = (const float*)d_in[7];
    const float* var1   = (const float*)d_in[8];
    const float* W1     = (const float*)d_in[9];
    const float* b1     = (const float*)d_in[10];
    const float* gamma2 = (const float*)d_in[11];
    const float* beta2  = (const float*)d_in[12];
    const float* mean2  = (const float*)d_in[13];
    const float* var2   = (const float*)d_in[14];
    const float* relc   = (const float*)d_in[15];
    const float* ck     = (const float*)d_in[16];
    const float* Wd     = (const float*)d_in[17];
    const float* bd     = (const float*)d_in[18];
    float* out = (float*)d_out;

    const int n = in_sizes[0] / DIM;     // 50000
    const int e = in_sizes[1];           // 640000

    cudaFuncSetAttribute(gemm128_a,    cudaFuncAttributeMaxDynamicSharedMemorySize, GEMM_SMEM);
    cudaFuncSetAttribute(gemm128_norm, cudaFuncAttributeMaxDynamicSharedMemorySize, GEMM_SMEM);

    // __device__ symbols are NOT valid host-side pointers — fetch device addresses.
    float *ev, *Wp1, *Wpd, *b1p;
    uint2 *hWh, *y1h, *zh;
    cudaGetSymbolAddress((void**)&hWh, g_hWh);
    cudaGetSymbolAddress((void**)&y1h, g_y1h);
    cudaGetSymbolAddress((void**)&zh,  g_zh);
    cudaGetSymbolAddress((void**)&ev,  g_ev);
    cudaGetSymbolAddress((void**)&Wp1, g_Wp1);
    cudaGetSymbolAddress((void**)&Wpd, g_Wpd);
    cudaGetSymbolAddress((void**)&b1p, g_b1p);

    int prep_threads = (n + 1 > SW_FLOATS) ? n + 1 : SW_FLOATS;
    prep_all<<<(prep_threads + 255) / 256, 256>>>(gamma1, beta1, mean1, var1,
                                                  gamma2, beta2, mean2, var2,
                                                  W1, Wd, rows, n, e);

    int gemm_blocks = (n + TM - 1) / TM;
    gemm128_a<<<gemm_blocks, 256, GEMM_SMEM>>>(x, Wp1, b1p, (__half2*)hWh, n);

    int warp_blocks = (n * 32 + 255) / 256;
    spmm_tanh<<<warp_blocks, 256>>>(hWh, cols, adj, rel, relc, b1, y1h, n);
    spmm_rgin<<<warp_blocks, 256>>>(y1h, cols, ev, ck, zh, n);

    gemm128_norm<<<gemm_blocks, 256, GEMM_SMEM>>>(zh, Wpd, bd, x, y1h, out, n);
}